// round 17
// baseline (speedup 1.0000x reference)
#include <cuda_runtime.h>
#include <cuda_bf16.h>
#include <math.h>

#define NN 50000
#define NE 800000
#define NEL 850000
#define DF 128
#define DLIN 512
#define DOUT 4
#define NBLK 49   // ceil(NN/1024)
#define XW 64     // DF/2 packed words per row
#define YW 256    // DLIN/2 packed words per row

// ---------------- device scratch ----------------
__device__ __align__(16) float g_h[NN * DF];
__device__ __align__(16) unsigned g_xhi[NN * XW];
__device__ __align__(16) unsigned g_xlo[NN * XW];
__device__ __align__(16) unsigned g_y0hi[NN * YW];
__device__ __align__(16) unsigned g_y0lo[NN * YW];
__device__ __align__(16) unsigned g_y1hi[NN * YW];
__device__ __align__(16) unsigned g_y1lo[NN * YW];
// packed weights
__device__ __align__(16) unsigned g_wchi[3 * 64 * 128];
__device__ __align__(16) unsigned g_wclo[3 * 64 * 128];
__device__ __align__(16) unsigned g_w0hi[64 * 512];
__device__ __align__(16) unsigned g_w0lo[64 * 512];
__device__ __align__(16) unsigned g_w1hi[256 * 512];
__device__ __align__(16) unsigned g_w1lo[256 * 512];
__device__ __align__(16) unsigned g_w2hi[256 * 512];
__device__ __align__(16) unsigned g_w2lo[256 * 512];
// attention / edges / CSR
__device__ __align__(16) float g_es[NN];
__device__ __align__(16) float g_ed[NN];
__device__ __align__(16) int g_src[NEL];
__device__ __align__(16) int g_dst[NEL];
__device__ __align__(16) int g_deg[NN];
__device__ __align__(16) int g_incl[NN];
__device__ __align__(16) int g_bsum[NBLK];
__device__ __align__(16) int g_boff[NBLK];
__device__ __align__(16) int g_rowstart[NN + 1];
__device__ __align__(16) int g_cursor[NN];
__device__ __align__(16) int g_csr[NEL];
__device__ int g_is64;

// ---------------- helpers ----------------
__device__ __forceinline__ float leaky(float v) { return v > 0.f ? v : 0.2f * v; }

// pack(e_lo -> low16 [even k], e_hi -> high16 [odd k])
__device__ __forceinline__ unsigned pack_bf16x2(float e_lo, float e_hi) {
    unsigned r;
    asm("cvt.rn.bf16x2.f32 %0, %1, %2;" : "=r"(r) : "f"(e_hi), "f"(e_lo));
    return r;
}
__device__ __forceinline__ void split_bf16(float v, float& hi, float& lo) {
    __nv_bfloat16 h = __float2bfloat16_rn(v);
    hi = __bfloat162float(h);
    lo = v - hi;
}

// ---------------- edge dtype probe / edge build ----------------
__global__ void k_detect_dtype(const int* __restrict__ ei32) {
    if (threadIdx.x != 0 || blockIdx.x != 0) return;
    int zeros = 0;
    for (int i = 0; i < 256; i++)
        if (ei32[2 * i + 1] == 0) zeros++;
    g_is64 = (zeros >= 250) ? 1 : 0;
}

__global__ void k_build_edges(const void* __restrict__ ei) {
    int i = blockIdx.x * blockDim.x + threadIdx.x;
    if (i >= NEL) return;
    int s, d;
    if (i < NE) {
        if (g_is64) {
            const long long* p = (const long long*)ei;
            s = (int)p[i];
            d = (int)p[NE + i];
        } else {
            const int* p = (const int*)ei;
            s = p[i];
            d = p[NE + i];
        }
        s = min(max(s, 0), NN - 1);
        d = min(max(d, 0), NN - 1);
    } else {
        s = i - NE;
        d = i - NE;
    }
    g_src[i] = s;
    g_dst[i] = d;
}

// ---------------- CSR build ----------------
__global__ void k_zero_deg() {
    int i = blockIdx.x * blockDim.x + threadIdx.x;
    if (i < NN) g_deg[i] = 0;
}
__global__ void k_hist() {
    int e = blockIdx.x * blockDim.x + threadIdx.x;
    if (e >= NEL) return;
    atomicAdd(&g_deg[g_dst[e]], 1);
}
__global__ void k_scan1() {
    __shared__ int sm[1024];
    int i = blockIdx.x * 1024 + threadIdx.x;
    int v = (i < NN) ? g_deg[i] : 0;
    sm[threadIdx.x] = v;
    __syncthreads();
    for (int off = 1; off < 1024; off <<= 1) {
        int t = (threadIdx.x >= off) ? sm[threadIdx.x - off] : 0;
        __syncthreads();
        sm[threadIdx.x] += t;
        __syncthreads();
    }
    if (i < NN) g_incl[i] = sm[threadIdx.x];
    if (threadIdx.x == 1023) g_bsum[blockIdx.x] = sm[1023];
}
__global__ void k_scan2() {
    if (threadIdx.x == 0 && blockIdx.x == 0) {
        int run = 0;
        for (int b = 0; b < NBLK; b++) {
            int t = g_bsum[b];
            g_boff[b] = run;
            run += t;
        }
    }
}
__global__ void k_scan3() {
    int i = blockIdx.x * blockDim.x + threadIdx.x;
    if (i < NN) {
        int rs = g_incl[i] - g_deg[i] + g_boff[i >> 10];
        g_rowstart[i] = rs;
        g_cursor[i] = rs;
    }
    if (i == 0) g_rowstart[NN] = NEL;
}
__global__ void k_scatter() {
    int e = blockIdx.x * blockDim.x + threadIdx.x;
    if (e >= NEL) return;
    int pos = atomicAdd(&g_cursor[g_dst[e]], 1);
    g_csr[pos] = g_src[e];
}

// ---------------- packing prepasses ----------------
// A-side: x [M][K] -> packed [M][K/2]
__global__ void k_pack_a(const float* __restrict__ X, unsigned* __restrict__ hi,
                         unsigned* __restrict__ lo, int total, int K2) {
    int idx = blockIdx.x * blockDim.x + threadIdx.x;
    if (idx >= total) return;
    int m = idx / K2, k2 = idx - m * K2;
    float2 v = *(const float2*)(X + (size_t)m * (2 * K2) + 2 * k2);
    float h0, l0, h1, l1;
    split_bf16(v.x, h0, l0);
    split_bf16(v.y, h1, l1);
    hi[idx] = pack_bf16x2(h0, h1);
    lo[idx] = pack_bf16x2(l0, l1);
}
// B-side: W [K][N] -> packed word(k2,n) at [k2*N+n]
__global__ void k_pack_b(const float* __restrict__ W, unsigned* __restrict__ hi,
                         unsigned* __restrict__ lo, int K2, int N) {
    int idx = blockIdx.x * blockDim.x + threadIdx.x;
    if (idx >= K2 * N) return;
    int k2 = idx / N, n = idx - k2 * N;
    float a = W[(size_t)(2 * k2) * N + n];
    float b = W[(size_t)(2 * k2 + 1) * N + n];
    float ha, la, hb, lb;
    split_bf16(a, ha, la);
    split_bf16(b, hb, lb);
    hi[idx] = pack_bf16x2(ha, hb);
    lo[idx] = pack_bf16x2(la, lb);
}

// ---------------- split-BF16 tensor-core GEMM (pre-packed, cp.async double-buffered) ----------------
#define AW_STRIDE 20
#define BW_STRIDE 136
#define AH_OFF 0
#define AL_OFF 2560
#define BH_OFF 5120
#define BL_OFF 7296
#define BUF_WORDS 9472
#define SMEM_MMA (2 * BUF_WORDS * 4)

#define MMA_BF16(ACC, A0, A1, A2, A3, B0, B1)                                    \
    asm volatile(                                                                 \
        "mma.sync.aligned.m16n8k16.row.col.f32.bf16.bf16.f32 "                    \
        "{%0,%1,%2,%3}, {%4,%5,%6,%7}, {%8,%9}, {%0,%1,%2,%3};"                   \
        : "+f"((ACC)[0]), "+f"((ACC)[1]), "+f"((ACC)[2]), "+f"((ACC)[3])          \
        : "r"(A0), "r"(A1), "r"(A2), "r"(A3), "r"(B0), "r"(B1))

__global__ __launch_bounds__(256, 2) void k_mma(
    const unsigned* __restrict__ Ahi, const unsigned* __restrict__ Alo,
    const unsigned* __restrict__ Bhi, const unsigned* __restrict__ Blo,
    const float* __restrict__ bias, float* __restrict__ Cf,
    unsigned* __restrict__ Chi, unsigned* __restrict__ Clo,
    int M, int N, int K, int act) {
    extern __shared__ unsigned smem[];
    unsigned sbase = (unsigned)__cvta_generic_to_shared(smem);

    const int tid = threadIdx.x;
    const int wid = tid >> 5;
    const int lane = tid & 31;
    const int warpM = wid >> 2;
    const int warpN = wid & 3;
    const int rowBase = blockIdx.y * 128;
    const int colBase = blockIdx.x * 128;
    const int lq = lane >> 2;
    const int lr = lane & 3;
    const int KW = K >> 1;

    float acc[4][4][4];
#pragma unroll
    for (int i = 0; i < 4; i++)
#pragma unroll
        for (int j = 0; j < 4; j++)
#pragma unroll
            for (int r = 0; r < 4; r++) acc[i][j][r] = 0.f;

    // loader mappings
    const int aChunk = tid & 3;          // 4 x 16B chunks cover 16 words/row
    const int aRowL = tid >> 2;          // 0..63 (+64)
    const int bChunk = tid & 31;         // 32 chunks cover 128 words/row
    const int bRowL = tid >> 5;          // 0..7 (+8)
    size_t aRowG[2];
#pragma unroll
    for (int i = 0; i < 2; i++) {
        int gr = rowBase + aRowL + i * 64;
        if (gr >= M) gr = M - 1;
        aRowG[i] = (size_t)gr;
    }

#define CPA(dstw, srcp) \
    asm volatile("cp.async.cg.shared.global [%0], [%1], 16;" :: "r"(sbase + (unsigned)(dstw) * 4u), "l"(srcp))

#define ISSUE_TILE(bufIdx, tw)                                                          \
    do {                                                                                \
        unsigned _b = (bufIdx) * BUF_WORDS;                                             \
        _Pragma("unroll")                                                               \
        for (int _i = 0; _i < 2; _i++) {                                                \
            int _rl = aRowL + _i * 64;                                                  \
            size_t _srow = aRowG[_i] * KW + (tw) + aChunk * 4;                          \
            CPA(_b + AH_OFF + _rl * AW_STRIDE + aChunk * 4, Ahi + _srow);               \
            CPA(_b + AL_OFF + _rl * AW_STRIDE + aChunk * 4, Alo + _srow);               \
        }                                                                               \
        _Pragma("unroll")                                                               \
        for (int _i = 0; _i < 2; _i++) {                                                \
            int _k2 = bRowL + _i * 8;                                                   \
            size_t _srow = (size_t)((tw) + _k2) * N + colBase + bChunk * 4;             \
            CPA(_b + BH_OFF + _k2 * BW_STRIDE + bChunk * 4, Bhi + _srow);               \
            CPA(_b + BL_OFF + _k2 * BW_STRIDE + bChunk * 4, Blo + _srow);               \
        }                                                                               \
    } while (0)

    const int nk = K >> 5;
    ISSUE_TILE(0, 0);
    asm volatile("cp.async.commit_group;");

    for (int t = 0; t < nk; t++) {
        if (t + 1 < nk) ISSUE_TILE((t + 1) & 1, (t + 1) * 16);
        asm volatile("cp.async.commit_group;");
        asm volatile("cp.async.wait_group 1;");
        __syncthreads();

        const unsigned base = (t & 1) * BUF_WORDS;
        const unsigned* AsH = smem + base + AH_OFF;
        const unsigned* AsL = smem + base + AL_OFF;
        const unsigned* BsH = smem + base + BH_OFF;
        const unsigned* BsL = smem + base + BL_OFF;

#pragma unroll
        for (int kk = 0; kk < 2; kk++) {
            const int kw = kk * 8;
            unsigned bh[4][2], bl[4][2];
#pragma unroll
            for (int nt = 0; nt < 4; nt++) {
                int c = warpN * 32 + nt * 8 + lq;
                bh[nt][0] = BsH[(kw + lr) * BW_STRIDE + c];
                bh[nt][1] = BsH[(kw + lr + 4) * BW_STRIDE + c];
                bl[nt][0] = BsL[(kw + lr) * BW_STRIDE + c];
                bl[nt][1] = BsL[(kw + lr + 4) * BW_STRIDE + c];
            }
#pragma unroll
            for (int mt = 0; mt < 4; mt++) {
                int r = warpM * 64 + mt * 16 + lq;
                int i0 = r * AW_STRIDE + kw + lr;
                int i1 = (r + 8) * AW_STRIDE + kw + lr;
                unsigned ah0 = AsH[i0], ah1 = AsH[i1], ah2 = AsH[i0 + 4], ah3 = AsH[i1 + 4];
                unsigned al0 = AsL[i0], al1 = AsL[i1], al2 = AsL[i0 + 4], al3 = AsL[i1 + 4];
#pragma unroll
                for (int nt = 0; nt < 4; nt++) {
                    MMA_BF16(acc[mt][nt], al0, al1, al2, al3, bh[nt][0], bh[nt][1]);
                    MMA_BF16(acc[mt][nt], ah0, ah1, ah2, ah3, bl[nt][0], bl[nt][1]);
                    MMA_BF16(acc[mt][nt], ah0, ah1, ah2, ah3, bh[nt][0], bh[nt][1]);
                }
            }
        }
        __syncthreads();
    }

    const int NW = N >> 1;
#pragma unroll
    for (int mt = 0; mt < 4; mt++) {
        int r0 = rowBase + warpM * 64 + mt * 16 + lq;
#pragma unroll
        for (int nt = 0; nt < 4; nt++) {
            int c = colBase + warpN * 32 + nt * 8 + lr * 2;
            float b0 = bias ? bias[c] : 0.f;
            float b1 = bias ? bias[c + 1] : 0.f;
            float v0 = acc[mt][nt][0] + b0;
            float v1 = acc[mt][nt][1] + b1;
            float v2 = acc[mt][nt][2] + b0;
            float v3 = acc[mt][nt][3] + b1;
            if (act) {
                v0 = fmaxf(v0, 0.f); v1 = fmaxf(v1, 0.f);
                v2 = fmaxf(v2, 0.f); v3 = fmaxf(v3, 0.f);
            }
            if (Cf) {
                if (r0 < M) *(float2*)(Cf + (size_t)r0 * N + c) = make_float2(v0, v1);
                if (r0 + 8 < M) *(float2*)(Cf + (size_t)(r0 + 8) * N + c) = make_float2(v2, v3);
            } else {
                int wc = c >> 1;
                if (r0 < M) {
                    float h0, l0, h1, l1;
                    split_bf16(v0, h0, l0);
                    split_bf16(v1, h1, l1);
                    Chi[(size_t)r0 * NW + wc] = pack_bf16x2(h0, h1);
                    Clo[(size_t)r0 * NW + wc] = pack_bf16x2(l0, l1);
                }
                if (r0 + 8 < M) {
                    float h2, l2, h3, l3;
                    split_bf16(v2, h2, l2);
                    split_bf16(v3, h3, l3);
                    Chi[(size_t)(r0 + 8) * NW + wc] = pack_bf16x2(h2, h3);
                    Clo[(size_t)(r0 + 8) * NW + wc] = pack_bf16x2(l2, l3);
                }
            }
        }
    }
#undef ISSUE_TILE
#undef CPA
}

// ---------------- per-node attention scalars ----------------
__global__ void k_es_ed(const float* __restrict__ a_src, const float* __restrict__ a_dst) {
    int n = blockIdx.x * (blockDim.x >> 5) + (threadIdx.x >> 5);
    int lane = threadIdx.x & 31;
    if (n >= NN) return;
    float4 hv = *(const float4*)(g_h + (size_t)n * DF + lane * 4);
    float4 as = *(const float4*)(a_src + lane * 4);
    float4 ad = *(const float4*)(a_dst + lane * 4);
    float s = hv.x * as.x + hv.y * as.y + hv.z * as.z + hv.w * as.w;
    float d = hv.x * ad.x + hv.y * ad.y + hv.z * ad.z + hv.w * ad.w;
#pragma unroll
    for (int o = 16; o > 0; o >>= 1) {
        s += __shfl_xor_sync(0xffffffff, s, o);
        d += __shfl_xor_sync(0xffffffff, d, o);
    }
    if (lane == 0) {
        g_es[n] = s;
        g_ed[n] = d;
    }
}

// ---------------- fused softmax + aggregation; writes packed x ----------------
__global__ void k_node_aggr(const float* __restrict__ bias) {
    int n = blockIdx.x * (blockDim.x >> 5) + (threadIdx.x >> 5);
    int lane = threadIdx.x & 31;
    if (n >= NN) return;
    int r0 = g_rowstart[n];
    int r1 = g_rowstart[n + 1];
    float edn = g_ed[n];

    float m = -1e30f;
    for (int i = r0 + lane; i < r1; i += 32)
        m = fmaxf(m, leaky(g_es[g_csr[i]] + edn));
#pragma unroll
    for (int o = 16; o > 0; o >>= 1)
        m = fmaxf(m, __shfl_xor_sync(0xffffffff, m, o));

    float s = 0.f;
    for (int i = r0 + lane; i < r1; i += 32)
        s += expf(leaky(g_es[g_csr[i]] + edn) - m);
#pragma unroll
    for (int o = 16; o > 0; o >>= 1)
        s += __shfl_xor_sync(0xffffffff, s, o);
    float inv = 1.f / s;

    float4 acc = make_float4(0.f, 0.f, 0.f, 0.f);
    for (int i = r0; i < r1; i++) {
        int src = g_csr[i];
        float w = expf(leaky(g_es[src] + edn) - m) * inv;
        float4 hv = *(const float4*)(g_h + (size_t)src * DF + lane * 4);
        acc.x += w * hv.x;
        acc.y += w * hv.y;
        acc.z += w * hv.z;
        acc.w += w * hv.w;
    }
    float4 bv = *(const float4*)(bias + lane * 4);
    float r0v = leaky(acc.x + bv.x);
    float r1v = leaky(acc.y + bv.y);
    float r2v = leaky(acc.z + bv.z);
    float r3v = leaky(acc.w + bv.w);
    float h0, l0, h1, l1, h2, l2, h3, l3;
    split_bf16(r0v, h0, l0);
    split_bf16(r1v, h1, l1);
    split_bf16(r2v, h2, l2);
    split_bf16(r3v, h3, l3);
    size_t base = (size_t)n * XW + 2 * lane;
    g_xhi[base]     = pack_bf16x2(h0, h1);
    g_xhi[base + 1] = pack_bf16x2(h2, h3);
    g_xlo[base]     = pack_bf16x2(l0, l1);
    g_xlo[base + 1] = pack_bf16x2(l2, l3);
}

// ---------------- output head (packed input) ----------------
__global__ void k_out(const unsigned* __restrict__ Yhi, const unsigned* __restrict__ Ylo,
                      const float* __restrict__ Wout, const float* __restrict__ bout,
                      float* __restrict__ out) {
    int n = blockIdx.x * (blockDim.x >> 5) + (threadIdx.x >> 5);
    int lane = threadIdx.x & 31;
    if (n >= NN) return;
    float acc0 = 0.f, acc1 = 0.f, acc2 = 0.f, acc3 = 0.f;
    const unsigned* yh = Yhi + (size_t)n * YW;
    const unsigned* yl = Ylo + (size_t)n * YW;
    for (int w = lane; w < YW; w += 32) {
        unsigned hw = yh[w], lw = yl[w];
        float2 h = __bfloat1622float2(*(const __nv_bfloat162*)&hw);
        float2 l = __bfloat1622float2(*(const __nv_bfloat162*)&lw);
        float v0 = h.x + l.x;
        float v1 = h.y + l.y;
        int k = 2 * w;
        float4 w0 = *(const float4*)(Wout + (size_t)k * 4);
        float4 w1 = *(const float4*)(Wout + (size_t)(k + 1) * 4);
        acc0 += v0 * w0.x + v1 * w1.x;
        acc1 += v0 * w0.y + v1 * w1.y;
        acc2 += v0 * w0.z + v1 * w1.z;
        acc3 += v0 * w0.w + v1 * w1.w;
    }
#pragma unroll
    for (int o = 16; o > 0; o >>= 1) {
        acc0 += __shfl_xor_sync(0xffffffff, acc0, o);
        acc1 += __shfl_xor_sync(0xffffffff, acc1, o);
        acc2 += __shfl_xor_sync(0xffffffff, acc2, o);
        acc3 += __shfl_xor_sync(0xffffffff, acc3, o);
    }
    if (lane == 0) {
        float4 r;
        r.x = acc0 + bout[0];
        r.y = acc1 + bout[1];
        r.z = acc2 + bout[2];
        r.w = acc3 + bout[3];
        *(float4*)(out + (size_t)n * 4) = r;
    }
}

extern "C" void kernel_launch(void* const* d_in, const int* in_sizes, int n_in,
                              void* d_out, int out_size) {
    const float *x, *conv_W, *conv_as, *conv_ad, *conv_b;
    const float *lin_W0, *lin_b0, *lin_W1, *lin_b1, *lin_W2, *lin_b2, *lin_Wout, *lin_bout;
    const void* ei;

    if (in_sizes[0] == NN * DF) {
        x        = (const float*)d_in[0];
        ei       = d_in[1];
        conv_W   = (const float*)d_in[2];
        conv_as  = (const float*)d_in[3];
        conv_ad  = (const float*)d_in[4];
        conv_b   = (const float*)d_in[5];
        lin_W0   = (const float*)d_in[6];
        lin_b0   = (const float*)d_in[7];
        lin_W1   = (const float*)d_in[8];
        lin_b1   = (const float*)d_in[9];
        lin_W2   = (const float*)d_in[10];
        lin_b2   = (const float*)d_in[11];
        lin_Wout = (const float*)d_in[12];
        lin_bout = (const float*)d_in[13];
    } else {
        conv_W   = (const float*)d_in[0];
        conv_ad  = (const float*)d_in[1];
        conv_as  = (const float*)d_in[2];
        conv_b   = (const float*)d_in[3];
        ei       = d_in[4];
        lin_W0   = (const float*)d_in[5];
        lin_W1   = (const float*)d_in[6];
        lin_W2   = (const float*)d_in[7];
        lin_Wout = (const float*)d_in[8];
        lin_b0   = (const float*)d_in[9];
        lin_b1   = (const float*)d_in[10];
        lin_b2   = (const float*)d_in[11];
        lin_bout = (const float*)d_in[12];
        x        = (const float*)d_in[13];
    }
    float* out = (float*)d_out;

    void *p_h, *p_xhi, *p_xlo, *p_y0hi, *p_y0lo, *p_y1hi, *p_y1lo;
    void *p_wchi, *p_wclo, *p_w0hi, *p_w0lo, *p_w1hi, *p_w1lo, *p_w2hi, *p_w2lo;
    cudaGetSymbolAddress(&p_h, g_h);
    cudaGetSymbolAddress(&p_xhi, g_xhi);
    cudaGetSymbolAddress(&p_xlo, g_xlo);
    cudaGetSymbolAddress(&p_y0hi, g_y0hi);
    cudaGetSymbolAddress(&p_y0lo, g_y0lo);
    cudaGetSymbolAddress(&p_y1hi, g_y1hi);
    cudaGetSymbolAddress(&p_y1lo, g_y1lo);
    cudaGetSymbolAddress(&p_wchi, g_wchi);
    cudaGetSymbolAddress(&p_wclo, g_wclo);
    cudaGetSymbolAddress(&p_w0hi, g_w0hi);
    cudaGetSymbolAddress(&p_w0lo, g_w0lo);
    cudaGetSymbolAddress(&p_w1hi, g_w1hi);
    cudaGetSymbolAddress(&p_w1lo, g_w1lo);
    cudaGetSymbolAddress(&p_w2hi, g_w2hi);
    cudaGetSymbolAddress(&p_w2lo, g_w2lo);

    static int smem_set = 0;
    if (!smem_set) {
        cudaFuncSetAttribute(k_mma, cudaFuncAttributeMaxDynamicSharedMemorySize, SMEM_MMA);
        smem_set = 1;
    }

    // edges + CSR
    k_detect_dtype<<<1, 32>>>((const int*)ei);
    k_build_edges<<<(NEL + 255) / 256, 256>>>(ei);
    k_zero_deg<<<(NN + 255) / 256, 256>>>();
    k_hist<<<(NEL + 255) / 256, 256>>>();
    k_scan1<<<NBLK, 1024>>>();
    k_scan2<<<1, 32>>>();
    k_scan3<<<(NN + 255) / 256, 256>>>();
    k_scatter<<<(NEL + 255) / 256, 256>>>();

    // pack weights + input x
    for (int l = 0; l < 3; l++)
        k_pack_b<<<(64 * 128 + 255) / 256, 256>>>(conv_W + (size_t)l * DF * DF,
                                                  (unsigned*)p_wchi + l * 64 * 128,
                                                  (unsigned*)p_wclo + l * 64 * 128, 64, 128);
    k_pack_b<<<(64 * 512 + 255) / 256, 256>>>(lin_W0, (unsigned*)p_w0hi, (unsigned*)p_w0lo, 64, 512);
    k_pack_b<<<(256 * 512 + 255) / 256, 256>>>(lin_W1, (unsigned*)p_w1hi, (unsigned*)p_w1lo, 256, 512);
    k_pack_b<<<(256 * 512 + 255) / 256, 256>>>(lin_W2, (unsigned*)p_w2hi, (unsigned*)p_w2lo, 256, 512);
    k_pack_a<<<(NN * XW + 255) / 256, 256>>>(x, (unsigned*)p_xhi, (unsigned*)p_xlo, NN * XW, XW);

    dim3 grid128(1, (NN + 127) / 128);
    dim3 grid512(DLIN / 128, (NN + 127) / 128);
    const int wpb = 8;
    const int nodeBlocks = (NN + wpb - 1) / wpb;

    for (int layer = 0; layer < 3; layer++) {
        const float* as = conv_as + (size_t)layer * DF;
        const float* ad = conv_ad + (size_t)layer * DF;
        const float* b  = conv_b + (size_t)layer * DF;

        k_mma<<<grid128, 256, SMEM_MMA>>>(
            (const unsigned*)p_xhi, (const unsigned*)p_xlo,
            (const unsigned*)p_wchi + layer * 64 * 128, (const unsigned*)p_wclo + layer * 64 * 128,
            nullptr, (float*)p_h, nullptr, nullptr, NN, DF, DF, 0);
        k_es_ed<<<nodeBlocks, wpb * 32>>>(as, ad);
        k_node_aggr<<<nodeBlocks, wpb * 32>>>(b);
    }

    // MLP (packed chain)
    k_mma<<<grid512, 256, SMEM_MMA>>>(
        (const unsigned*)p_xhi, (const unsigned*)p_xlo,
        (const unsigned*)p_w0hi, (const unsigned*)p_w0lo,
        lin_b0, nullptr, (unsigned*)p_y0hi, (unsigned*)p_y0lo, NN, DLIN, DF, 1);
    k_mma<<<grid512, 256, SMEM_MMA>>>(
        (const unsigned*)p_y0hi, (const unsigned*)p_y0lo,
        (const unsigned*)p_w1hi, (const unsigned*)p_w1lo,
        lin_b1, nullptr, (unsigned*)p_y1hi, (unsigned*)p_y1lo, NN, DLIN, DLIN, 1);
    k_mma<<<grid512, 256, SMEM_MMA>>>(
        (const unsigned*)p_y1hi, (const unsigned*)p_y1lo,
        (const unsigned*)p_w2hi, (const unsigned*)p_w2lo,
        lin_b2, nullptr, (unsigned*)p_y0hi, (unsigned*)p_y0lo, NN, DLIN, DLIN, 1);
    k_out<<<nodeBlocks, wpb * 32>>>((const unsigned*)p_y0hi, (const unsigned*)p_y0lo,
                                    lin_Wout, lin_bout, out);
}